// round 1
// baseline (speedup 1.0000x reference)
#include <cuda_runtime.h>

#define NB 2
#define NN 512
#define NE 128
#define NH 256

// scratch (allocation-free rule: __device__ globals)
__device__ float g_P[NB * NN * NH];     // hi @ W1[0:128]
__device__ float g_Q[NB * NN * NH];     // hj @ W1[128:256]
__device__ float g_raw[NB * NN * NN];   // pre-symmetrization output

// ---------------- packed f32x2 helpers (sm_103a FFMA2) ----------------
__device__ __forceinline__ void ffma2(unsigned long long& d,
                                      unsigned long long a,
                                      unsigned long long b) {
    asm("fma.rn.f32x2 %0, %1, %2, %0;" : "+l"(d) : "l"(a), "l"(b));
}
__device__ __forceinline__ unsigned long long bcast2(float a) {
    unsigned long long r;
    asm("mov.b64 %0, {%1, %1};" : "=l"(r) : "f"(a));
    return r;
}
__device__ __forceinline__ unsigned long long pack2(float lo, float hi) {
    unsigned long long r;
    asm("mov.b64 %0, {%1, %2};" : "=l"(r) : "f"(lo), "f"(hi));
    return r;
}
__device__ __forceinline__ float2 unpack2(unsigned long long v) {
    float2 f;
    asm("mov.b64 {%0, %1}, %2;" : "=f"(f.x), "=f"(f.y) : "l"(v));
    return f;
}

// ---------------- phase A: P,Q precompute (tiny GEMMs) ----------------
__global__ void precompute_pq(const float* __restrict__ node,
                              const float* __restrict__ W1) {
    const int row = blockIdx.x;   // 0 .. B*N-1
    const int t = threadIdx.x;    // 0 .. 255 (h)
    __shared__ float ns[NE];
    if (t < NE) ns[t] = node[row * NE + t];
    __syncthreads();
    float p = 0.f, q = 0.f;
#pragma unroll 8
    for (int e = 0; e < NE; e++) {
        float nv = ns[e];
        p = fmaf(nv, W1[e * NH + t], p);
        q = fmaf(nv, W1[(NE + e) * NH + t], q);
    }
    g_P[row * NH + t] = p;
    g_Q[row * NH + t] = q;
}

// ---------------- phase B: fused edge MLP ----------------
// block = 256 threads, tile = 8 i-rows x 8 j-cols (64 pairs) x 256 H
// thread t: pg = t>>5 (i-row within tile, = warp id), hg = t&31 (8 H cols)
#define SMEM_FLOATS (2048 + 8192 + 16384 + 4 * 256 + 64)
#define SMEM_BYTES (SMEM_FLOATS * 4)

__global__ void __launch_bounds__(256, 2)
edge_mlp(const float* __restrict__ node, const float* __restrict__ euclid,
         const float* __restrict__ W1, const float* __restrict__ b1,
         const float* __restrict__ W2, const float* __restrict__ b2,
         const float* __restrict__ W3, const float* __restrict__ b3) {
    extern __shared__ float sm[];
    float* habs_s = sm;              // [32 e][64 p]
    float* ws     = sm + 2048;       // [32 k][256 h] weight chunk
    float* h1s    = ws + 8192;       // [64 p][256 h]
    float* w1e_s  = h1s + 16384;     // [256] W1 row 384 (euclid coeff)
    float* b1_s   = w1e_s + 256;
    float* b2_s   = b1_s + 256;
    float* w3_s   = b2_s + 256;
    float* d_s    = w3_s + 256;      // [64] euclid values of the tile

    const int b  = blockIdx.z;
    const int i0 = blockIdx.y << 3;
    const int j0 = blockIdx.x << 3;
    const int t  = threadIdx.x;
    const int pg = t >> 5;    // i-row within tile
    const int hg = t & 31;
    const int h0 = hg << 3;   // first of 8 h columns

    // stage small vectors
    w1e_s[t] = W1[384 * NH + t];
    b1_s[t]  = b1[t];
    b2_s[t]  = b2[t];
    w3_s[t]  = W3[t];
    if (t < 64) {
        int ii = t >> 3, jj = t & 7;
        d_s[t] = euclid[(b * NN + i0 + ii) * NN + j0 + jj];
    }
    __syncthreads();

    // ---- init acc = P[i] + Q[j] + d*W1[384] + b1 ----
    unsigned long long acc[8][4];
    {
        const float* Pr = g_P + (b * NN + i0 + pg) * NH + h0;
        float pv[8];
#pragma unroll
        for (int c = 0; c < 8; c++) pv[c] = Pr[c] + b1_s[h0 + c];
#pragma unroll
        for (int dp = 0; dp < 8; dp++) {
            const float* Qr = g_Q + (b * NN + j0 + dp) * NH + h0;
            float dv = d_s[(pg << 3) + dp];
#pragma unroll
            for (int c2 = 0; c2 < 4; c2++) {
                float lo = pv[2 * c2]     + Qr[2 * c2]     + dv * w1e_s[h0 + 2 * c2];
                float hi = pv[2 * c2 + 1] + Qr[2 * c2 + 1] + dv * w1e_s[h0 + 2 * c2 + 1];
                acc[dp][c2] = pack2(lo, hi);
            }
        }
    }

    // ---- layer 1: |hi-hj| @ W1[256:384]  (K = 128 in chunks of 32) ----
    for (int ek = 0; ek < NE; ek += 32) {
        // habs chunk: habs_s[e][p]
#pragma unroll
        for (int r = 0; r < 8; r++) {
            int idx = t + r * 256;
            int e = idx >> 6, p = idx & 63;
            float av = node[(b * NN + i0 + (p >> 3)) * NE + ek + e];
            float cv = node[(b * NN + j0 + (p & 7)) * NE + ek + e];
            habs_s[e * 64 + p] = fabsf(av - cv);
        }
        // W1c chunk (rows are contiguous in gmem)
        {
            const float4* src = (const float4*)(W1 + (256 + ek) * NH);
            float4* dst = (float4*)ws;
#pragma unroll
            for (int r = 0; r < 8; r++) dst[t + r * 256] = src[t + r * 256];
        }
        __syncthreads();
#pragma unroll 2
        for (int e = 0; e < 32; e++) {
            float4 a0 = *(const float4*)&habs_s[e * 64 + (pg << 3)];
            float4 a1 = *(const float4*)&habs_s[e * 64 + (pg << 3) + 4];
            ulonglong2 w01 = *(const ulonglong2*)&ws[e * NH + h0];
            ulonglong2 w23 = *(const ulonglong2*)&ws[e * NH + h0 + 4];
            unsigned long long av[8];
            av[0] = bcast2(a0.x); av[1] = bcast2(a0.y);
            av[2] = bcast2(a0.z); av[3] = bcast2(a0.w);
            av[4] = bcast2(a1.x); av[5] = bcast2(a1.y);
            av[6] = bcast2(a1.z); av[7] = bcast2(a1.w);
#pragma unroll
            for (int dp = 0; dp < 8; dp++) {
                ffma2(acc[dp][0], av[dp], w01.x);
                ffma2(acc[dp][1], av[dp], w01.y);
                ffma2(acc[dp][2], av[dp], w23.x);
                ffma2(acc[dp][3], av[dp], w23.y);
            }
        }
        __syncthreads();
    }

    // ---- relu -> h1s; reinit acc with b2 ----
#pragma unroll
    for (int dp = 0; dp < 8; dp++) {
        float2 v0 = unpack2(acc[dp][0]);
        float2 v1 = unpack2(acc[dp][1]);
        float2 v2 = unpack2(acc[dp][2]);
        float2 v3 = unpack2(acc[dp][3]);
        float4 o0 = make_float4(fmaxf(v0.x, 0.f), fmaxf(v0.y, 0.f),
                                fmaxf(v1.x, 0.f), fmaxf(v1.y, 0.f));
        float4 o1 = make_float4(fmaxf(v2.x, 0.f), fmaxf(v2.y, 0.f),
                                fmaxf(v3.x, 0.f), fmaxf(v3.y, 0.f));
        *(float4*)&h1s[((pg << 3) + dp) * NH + h0] = o0;
        *(float4*)&h1s[((pg << 3) + dp) * NH + h0 + 4] = o1;
#pragma unroll
        for (int c2 = 0; c2 < 4; c2++)
            acc[dp][c2] = pack2(b2_s[h0 + 2 * c2], b2_s[h0 + 2 * c2 + 1]);
    }
    __syncthreads();

    // ---- layer 2: h1 @ W2  (K = 256 in chunks of 32) ----
    for (int kk = 0; kk < NH; kk += 32) {
        {
            const float4* src = (const float4*)(W2 + kk * NH);
            float4* dst = (float4*)ws;
#pragma unroll
            for (int r = 0; r < 8; r++) dst[t + r * 256] = src[t + r * 256];
        }
        __syncthreads();
#pragma unroll 2
        for (int k = 0; k < 32; k++) {
            ulonglong2 w01 = *(const ulonglong2*)&ws[k * NH + h0];
            ulonglong2 w23 = *(const ulonglong2*)&ws[k * NH + h0 + 4];
#pragma unroll
            for (int dp = 0; dp < 8; dp++) {
                unsigned long long av = bcast2(h1s[((pg << 3) + dp) * NH + kk + k]);
                ffma2(acc[dp][0], av, w01.x);
                ffma2(acc[dp][1], av, w01.y);
                ffma2(acc[dp][2], av, w23.x);
                ffma2(acc[dp][3], av, w23.y);
            }
        }
        __syncthreads();
    }

    // ---- layer 3: relu then dot with W3, warp-reduce over 32 h-threads ----
    float part[8];
#pragma unroll
    for (int dp = 0; dp < 8; dp++) part[dp] = 0.f;
#pragma unroll
    for (int c2 = 0; c2 < 4; c2++) {
        float wl = w3_s[h0 + 2 * c2], wh = w3_s[h0 + 2 * c2 + 1];
#pragma unroll
        for (int dp = 0; dp < 8; dp++) {
            float2 v = unpack2(acc[dp][c2]);
            part[dp] = fmaf(fmaxf(v.x, 0.f), wl, part[dp]);
            part[dp] = fmaf(fmaxf(v.y, 0.f), wh, part[dp]);
        }
    }
#pragma unroll
    for (int dp = 0; dp < 8; dp++) {
#pragma unroll
        for (int off = 16; off; off >>= 1)
            part[dp] += __shfl_down_sync(0xffffffffu, part[dp], off);
    }
    if (hg == 0) {
        float b3v = b3[0];
#pragma unroll
        for (int dp = 0; dp < 8; dp++)
            g_raw[(b * NN + i0 + pg) * NN + j0 + dp] = part[dp] + b3v;
    }
}

// ---------------- phase C: symmetrize + zero diagonal ----------------
__global__ void symmetrize(float* __restrict__ out) {
    int idx = blockIdx.x * 256 + threadIdx.x;
    int b = idx >> 18;
    int r = idx & 262143;
    int i = r >> 9;
    int j = r & 511;
    float v = 0.f;
    if (i != j)
        v = 0.5f * (g_raw[idx] + g_raw[(b << 18) + (j << 9) + i]);
    out[idx] = v;
}

extern "C" void kernel_launch(void* const* d_in, const int* in_sizes, int n_in,
                              void* d_out, int out_size) {
    const float* node   = (const float*)d_in[0];
    // d_in[1] = problems (unused: euclid is provided)
    const float* euclid = (const float*)d_in[2];
    const float* W1 = (const float*)d_in[3];
    const float* b1 = (const float*)d_in[4];
    const float* W2 = (const float*)d_in[5];
    const float* b2 = (const float*)d_in[6];
    const float* W3 = (const float*)d_in[7];
    const float* b3 = (const float*)d_in[8];
    float* out = (float*)d_out;

    cudaFuncSetAttribute(edge_mlp, cudaFuncAttributeMaxDynamicSharedMemorySize,
                         SMEM_BYTES);

    precompute_pq<<<NB * NN, 256>>>(node, W1);
    dim3 grid(NN / 8, NN / 8, NB);
    edge_mlp<<<grid, 256, SMEM_BYTES>>>(node, euclid, W1, b1, W2, b2, W3, b3);
    symmetrize<<<(NB * NN * NN) / 256, 256>>>(out);
}

// round 4
// speedup vs baseline: 2.3852x; 2.3852x over previous
#include <cuda_runtime.h>
#include <cstdint>

#define NB 2
#define NN 512
#define NE 128
#define NH 256

// smem layout (bytes)
#define STRA 268            // floats per AB row (16B-aligned rows)
#define STRAB 1072          // STRA*4
#define STRB_B 144          // bytes per B row (36 floats)
#define BCHUNK_B 36864      // one B buffer: 256*144
#define OFF_B   137216      // AB = 128*1072
#define OFF_P   210944
#define OFF_W3  211968
#define OFF_NI  212992
#define OFF_RED 213504
#define SMEM_REQ 215552

// device scratch (allocation-free rule)
__device__ float g_P[NB * NN * NH];
__device__ float g_raw[NB * NN * NN];
__device__ float g_B1[9 * 256 * 32];   // [chunk][n][k] tf32-rounded, L1 weights
__device__ float g_B2[9 * 256 * 32];   // [chunk][n][k] tf32-rounded, L2 weights

// ---------------- PTX helpers (all target-portable, sm_80+) ----------------
__device__ __forceinline__ uint32_t smem_u32(const void* p) {
    uint32_t a;
    asm("{ .reg .u64 t; cvta.to.shared.u64 t, %1; cvt.u32.u64 %0, t; }" : "=r"(a) : "l"(p));
    return a;
}
__device__ __forceinline__ float tf32r(float x) {
    uint32_t o;
    asm("cvt.rna.tf32.f32 %0, %1;" : "=r"(o) : "f"(x));
    return __uint_as_float(o);
}
#define LDSM4(R, A) \
    asm volatile("ldmatrix.sync.aligned.m8n8.x4.shared.b16 {%0,%1,%2,%3}, [%4];" \
        : "=r"((R)[0]), "=r"((R)[1]), "=r"((R)[2]), "=r"((R)[3]) : "r"(A))
#define LDSM2(R, A) \
    asm volatile("ldmatrix.sync.aligned.m8n8.x2.shared.b16 {%0,%1}, [%2];" \
        : "=r"((R)[0]), "=r"((R)[1]) : "r"(A))
#define MMA_TF32(C, Ar, Br) \
    asm volatile("mma.sync.aligned.m16n8k8.row.col.f32.tf32.tf32.f32 " \
        "{%0,%1,%2,%3}, {%4,%5,%6,%7}, {%8,%9}, {%0,%1,%2,%3};" \
        : "+f"((C)[0]), "+f"((C)[1]), "+f"((C)[2]), "+f"((C)[3]) \
        : "r"((Ar)[0]), "r"((Ar)[1]), "r"((Ar)[2]), "r"((Ar)[3]), \
          "r"((Br)[0]), "r"((Br)[1]))
#define CP16(d, s)  asm volatile("cp.async.ca.shared.global [%0], [%1], 16;" :: "r"(d), "l"(s))
#define CPCOMMIT()  asm volatile("cp.async.commit_group;" ::: "memory")
#define CPWAIT1()   asm volatile("cp.async.wait_group 1;" ::: "memory")

// ---------------- prep kernels ----------------
__global__ void precompute_P(const float* __restrict__ node, const float* __restrict__ W1) {
    const int row = blockIdx.x;
    const int t = threadIdx.x;
    __shared__ float ns[NE];
    if (t < NE) ns[t] = node[row * NE + t];
    __syncthreads();
    float p = 0.f;
#pragma unroll 8
    for (int e = 0; e < NE; e++) p = fmaf(ns[e], W1[e * NH + t], p);
    g_P[row * NH + t] = p;
}

__global__ void prep_B(const float* __restrict__ W1, const float* __restrict__ b1,
                       const float* __restrict__ W2, const float* __restrict__ b2) {
    int idx = blockIdx.x * 256 + threadIdx.x;    // 0 .. 73727
    int c = idx >> 13;
    int n = (idx >> 5) & 255;
    int kk = idx & 31;
    float v1, v2;
    if (c < 4)       v1 = W1[(128 + c * 32 + kk) * NH + n];           // hj block
    else if (c < 8)  v1 = W1[(256 + (c - 4) * 32 + kk) * NH + n];     // habs block
    else             v1 = (kk == 0) ? W1[384 * NH + n]                 // w1e (A col = d)
                        : (kk == 1) ? b1[n] : 0.f;                     // b1  (A col = 1)
    if (c < 8)       v2 = W2[(c * 32 + kk) * NH + n];
    else             v2 = (kk == 0) ? b2[n] : 0.f;                     // b2  (A col = 1)
    g_B1[idx] = tf32r(v1);
    g_B2[idx] = tf32r(v2);
}

// ---------------- GEMM inner (one 32-wide K chunk or the 8-wide tail) ----------------
template <int NK>
__device__ __forceinline__ void mma_chunk(float (&acc)[4][8][4],
                                          uint32_t aK, uint32_t bBase) {
#pragma unroll
    for (int ks = 0; ks < NK; ks++) {
        uint32_t a[4][4], bf[8][2];
        uint32_t aa = aK + ks * 32;
        uint32_t ba = bBase + ks * 32;
#pragma unroll
        for (int mt = 0; mt < 4; mt++) LDSM4(a[mt], aa + mt * 17152);   // 16 rows * 1072
#pragma unroll
        for (int nt = 0; nt < 8; nt++) LDSM2(bf[nt], ba + nt * 1152);   // 8 rows * 144
#pragma unroll
        for (int mt = 0; mt < 4; mt++)
#pragma unroll
            for (int nt = 0; nt < 8; nt++) MMA_TF32(acc[mt][nt], a[mt], bf[nt]);
    }
}

// ---------------- main fused kernel ----------------
__global__ void __launch_bounds__(256, 1)
edge_mlp_mma(const float* __restrict__ node, const float* __restrict__ euclid,
             const float* __restrict__ W3, const float* __restrict__ b3) {
    extern __shared__ char smc[];
    float* AB    = (float*)smc;
    float* P_s   = (float*)(smc + OFF_P);
    float* w3_s  = (float*)(smc + OFF_W3);
    float* ni_s  = (float*)(smc + OFF_NI);
    float* red_s = (float*)(smc + OFF_RED);
    const uint32_t sb = smem_u32(smc);

    const int tid = threadIdx.x, L = tid & 31, wid = tid >> 5;
    const int mw = wid >> 2, nw = wid & 3;
    const int m0 = mw * 64, n0 = nw * 64;
    const int b = blockIdx.z, i = blockIdx.y, j0 = blockIdx.x << 7;

    // prefetch L1 chunk 0 -> buf0 (overlaps with A staging)
    {
        const float* src = g_B1;
#pragma unroll
        for (int r = 0; r < 8; r++) {
            int seg = tid + r * 256, n = seg >> 3, s = seg & 7;
            CP16(sb + OFF_B + n * 144 + s * 16, src + n * 32 + s * 4);
        }
        CPCOMMIT();
    }

    // stage small vectors
    P_s[tid]  = g_P[(b * NN + i) * NH + tid];
    w3_s[tid] = W3[tid];
    if (tid < NE) ni_s[tid] = node[(size_t)(b * NN + i) * NE + tid];
    __syncthreads();

    // stage A tile: rows = 128 pairs, cols [hj(128) | habs(128) | d | 1 | 0..]
    {
        int row = tid >> 1, half = tid & 1;
        const float4* nj = (const float4*)(node + (size_t)(b * NN + j0 + row) * NE);
        float* dst = AB + row * STRA + half * 128;
#pragma unroll 8
        for (int q = 0; q < 32; q++) {
            float4 v = nj[q];
            float4 o;
            if (half == 0) {
                o.x = tf32r(v.x); o.y = tf32r(v.y);
                o.z = tf32r(v.z); o.w = tf32r(v.w);
            } else {
                o.x = tf32r(fabsf(ni_s[q * 4 + 0] - v.x));
                o.y = tf32r(fabsf(ni_s[q * 4 + 1] - v.y));
                o.z = tf32r(fabsf(ni_s[q * 4 + 2] - v.z));
                o.w = tf32r(fabsf(ni_s[q * 4 + 3] - v.w));
            }
            *(float4*)(dst + q * 4) = o;
        }
        if (tid < 128) {
            float d = euclid[(size_t)(b * NN + i) * NN + j0 + tid];
            float* rr = AB + tid * STRA;
            rr[256] = tf32r(d); rr[257] = 1.0f;
            rr[258] = 0.f; rr[259] = 0.f; rr[260] = 0.f;
            rr[261] = 0.f; rr[262] = 0.f; rr[263] = 0.f;
        }
    }

    float acc[4][8][4];
#pragma unroll
    for (int mt = 0; mt < 4; mt++)
#pragma unroll
        for (int nt = 0; nt < 8; nt++)
#pragma unroll
            for (int r = 0; r < 4; r++) acc[mt][nt][r] = 0.f;

    // per-thread ldmatrix base addresses
    const uint32_t rowA = (L & 7) + ((L >> 3) & 1) * 8;
    const uint32_t colA = (L >> 4) * 16;
    const uint32_t aBase = sb + (m0 + rowA) * STRAB + colA;
    const uint32_t rowB = (L & 7);
    const uint32_t colB = ((L >> 3) & 1) * 16;
    const uint32_t bOff = (n0 + rowB) * STRB_B + colB;

    // ---- one GEMM layer: 8 full chunks + 1 tail chunk, double-buffered B ----
    // Race-free schedule per iter c:
    //   issue cp.async for chunk c+1 into buf (c+1)&1   (overlaps mma of c)
    //   wait_group 1  -> chunk c landed
    //   barrier       -> all warps see chunk c, all done with prior write target
    //   mma on buf c&1
    //   barrier       -> no warp may rewrite buf c&1 (iter c+1's target is (c+2)&1? no:
    //                    iter c+1 writes (c+2)&1 == c&1) until all reads of it finished
    auto gemm_layer = [&](const float* gB, const float* nextB, int phase) {
        for (int c = 0; c < 9; c++) {
            const float* pre = (c < 8) ? (gB + (c + 1) * 8192) : nextB;
            if (pre) {
                uint32_t dst = sb + OFF_B + (((c + 1 + phase) & 1) ? BCHUNK_B : 0);
#pragma unroll
                for (int r = 0; r < 8; r++) {
                    int seg = tid + r * 256, n = seg >> 3, s = seg & 7;
                    CP16(dst + n * 144 + s * 16, pre + n * 32 + s * 4);
                }
            }
            CPCOMMIT();
            CPWAIT1();
            __syncthreads();
            uint32_t bBase = sb + OFF_B + (((c + phase) & 1) ? BCHUNK_B : 0) + bOff;
            uint32_t aK = aBase + c * 128;   // c*4 ksteps * 32 bytes
            if (c < 8) mma_chunk<4>(acc, aK, bBase);
            else       mma_chunk<1>(acc, aK, bBase);
            __syncthreads();   // WAR fence: buffer c&1 gets rewritten at iter c+1
        }
    };

    gemm_layer(g_B1, g_B2, 0);   // at c==8 prefetches L2 chunk0 into buf1

    // ---- epilogue 1: h1 = relu(acc + P), tf32-round, overwrite AB in place ----
#pragma unroll
    for (int mt = 0; mt < 4; mt++) {
        int r0 = m0 + mt * 16 + (L >> 2);
#pragma unroll
        for (int nt = 0; nt < 8; nt++) {
            int cb = n0 + nt * 8 + (L & 3) * 2;
            float p0 = P_s[cb], p1 = P_s[cb + 1];
            float2 v0, v1;
            v0.x = tf32r(fmaxf(acc[mt][nt][0] + p0, 0.f));
            v0.y = tf32r(fmaxf(acc[mt][nt][1] + p1, 0.f));
            v1.x = tf32r(fmaxf(acc[mt][nt][2] + p0, 0.f));
            v1.y = tf32r(fmaxf(acc[mt][nt][3] + p1, 0.f));
            *(float2*)(AB + r0 * STRA + cb) = v0;
            *(float2*)(AB + (r0 + 8) * STRA + cb) = v1;
            acc[mt][nt][0] = 0.f; acc[mt][nt][1] = 0.f;
            acc[mt][nt][2] = 0.f; acc[mt][nt][3] = 0.f;
        }
    }
    if (tid < 128) {
        float* rr = AB + tid * STRA;
        rr[256] = 1.0f; rr[257] = 0.f;   // bias column for layer 2; rest already 0
    }
    __syncthreads();

    gemm_layer(g_B2, nullptr, 1);

    // ---- epilogue 2: out = relu(acc) . W3  (b2 already folded via GEMM) ----
    float w3c[16];
#pragma unroll
    for (int nt = 0; nt < 8; nt++) {
        int cb = n0 + nt * 8 + (L & 3) * 2;
        w3c[nt * 2] = w3_s[cb];
        w3c[nt * 2 + 1] = w3_s[cb + 1];
    }
    float rs[8];
#pragma unroll
    for (int mt = 0; mt < 4; mt++) {
        float s0 = 0.f, s1 = 0.f;
#pragma unroll
        for (int nt = 0; nt < 8; nt++) {
            s0 = fmaf(fmaxf(acc[mt][nt][0], 0.f), w3c[nt * 2], s0);
            s0 = fmaf(fmaxf(acc[mt][nt][1], 0.f), w3c[nt * 2 + 1], s0);
            s1 = fmaf(fmaxf(acc[mt][nt][2], 0.f), w3c[nt * 2], s1);
            s1 = fmaf(fmaxf(acc[mt][nt][3], 0.f), w3c[nt * 2 + 1], s1);
        }
        rs[mt * 2] = s0;
        rs[mt * 2 + 1] = s1;
    }
#pragma unroll
    for (int r = 0; r < 8; r++) {
        float v = rs[r];
        v += __shfl_xor_sync(0xffffffffu, v, 1);
        v += __shfl_xor_sync(0xffffffffu, v, 2);
        if ((L & 3) == 0) {
            int m = m0 + (r >> 1) * 16 + (r & 1) * 8 + (L >> 2);
            red_s[m * 4 + nw] = v;
        }
    }
    __syncthreads();
    if (tid < 128) {
        float o = red_s[tid * 4] + red_s[tid * 4 + 1] +
                  red_s[tid * 4 + 2] + red_s[tid * 4 + 3] + b3[0];
        g_raw[(size_t)(b * NN + i) * NN + j0 + tid] = o;
    }
}

// ---------------- symmetrize + zero diagonal ----------------
__global__ void symmetrize(float* __restrict__ out) {
    int idx = blockIdx.x * 256 + threadIdx.x;
    int b = idx >> 18;
    int r = idx & 262143;
    int i = r >> 9;
    int j = r & 511;
    float v = 0.f;
    if (i != j)
        v = 0.5f * (g_raw[idx] + g_raw[(b << 18) + (j << 9) + i]);
    out[idx] = v;
}

extern "C" void kernel_launch(void* const* d_in, const int* in_sizes, int n_in,
                              void* d_out, int out_size) {
    const float* node   = (const float*)d_in[0];
    const float* euclid = (const float*)d_in[2];
    const float* W1 = (const float*)d_in[3];
    const float* b1 = (const float*)d_in[4];
    const float* W2 = (const float*)d_in[5];
    const float* b2 = (const float*)d_in[6];
    const float* W3 = (const float*)d_in[7];
    const float* b3 = (const float*)d_in[8];
    float* out = (float*)d_out;

    cudaFuncSetAttribute(edge_mlp_mma, cudaFuncAttributeMaxDynamicSharedMemorySize,
                         SMEM_REQ);

    precompute_P<<<NB * NN, 256>>>(node, W1);
    prep_B<<<288, 256>>>(W1, b1, W2, b2);
    dim3 grid(NN / 128, NN, NB);
    edge_mlp_mma<<<grid, 256, SMEM_REQ>>>(node, euclid, W3, b3);
    symmetrize<<<(NB * NN * NN) / 256, 256>>>(out);
}

// round 5
// speedup vs baseline: 4.5158x; 1.8933x over previous
#include <cuda_runtime.h>
#include <cuda_fp16.h>
#include <cstdint>

#define NB 2
#define NN 512
#define NE 128
#define NH 256

// A tile: 128 rows x 296 halves (592 B stride, 37 segs -> conflict-free)
#define STRA_B 592
// B chunk: 256 n-rows x 32 k halves, padded to 80 B rows (5 segs -> conflict-free)
#define STRB_B 80
#define BCHUNK_B 20480
#define OFF_A   0
#define OFF_B   75776
#define OFF_P   116736
#define OFF_W3  117760
#define OFF_NI  118784
#define OFF_RED 119296
#define SMEM_REQ 121856

// device scratch (allocation-free rule)
__device__ float g_P[NB * NN * NH];      // hi @ W1[0:128]   exact fp32
__device__ float g_Q[NB * NN * NH];      // hj @ W1[128:256] exact fp32
__device__ float g_raw[NB * NN * NN];
__device__ __half g_B1h[5 * 256 * 32];   // L1 B: [chunk][n][k] fp16
__device__ __half g_B2h[9 * 256 * 32];   // L2 B: [chunk][n][k] fp16

// ---------------- PTX helpers ----------------
__device__ __forceinline__ uint32_t smem_u32(const void* p) {
    uint32_t a;
    asm("{ .reg .u64 t; cvta.to.shared.u64 t, %1; cvt.u32.u64 %0, t; }" : "=r"(a) : "l"(p));
    return a;
}
#define LDSM4(R, A) \
    asm volatile("ldmatrix.sync.aligned.m8n8.x4.shared.b16 {%0,%1,%2,%3}, [%4];" \
        : "=r"((R)[0]), "=r"((R)[1]), "=r"((R)[2]), "=r"((R)[3]) : "r"(A))
#define LDSM2(R, A) \
    asm volatile("ldmatrix.sync.aligned.m8n8.x2.shared.b16 {%0,%1}, [%2];" \
        : "=r"((R)[0]), "=r"((R)[1]) : "r"(A))
#define MMA_F16(C, Ar, Br) \
    asm volatile("mma.sync.aligned.m16n8k16.row.col.f32.f16.f16.f32 " \
        "{%0,%1,%2,%3}, {%4,%5,%6,%7}, {%8,%9}, {%0,%1,%2,%3};" \
        : "+f"((C)[0]), "+f"((C)[1]), "+f"((C)[2]), "+f"((C)[3]) \
        : "r"((Ar)[0]), "r"((Ar)[1]), "r"((Ar)[2]), "r"((Ar)[3]), \
          "r"((Br)[0]), "r"((Br)[1]))
#define CP16(d, s)  asm volatile("cp.async.ca.shared.global [%0], [%1], 16;" :: "r"(d), "l"(s))
#define CPCOMMIT()  asm volatile("cp.async.commit_group;" ::: "memory")
#define CPWAIT1()   asm volatile("cp.async.wait_group 1;" ::: "memory")

// ---------------- prep kernels ----------------
__global__ void precompute_PQ(const float* __restrict__ node, const float* __restrict__ W1) {
    const int row = blockIdx.x;
    const int t = threadIdx.x;
    __shared__ float ns[NE];
    if (t < NE) ns[t] = node[row * NE + t];
    __syncthreads();
    float p = 0.f, q = 0.f;
#pragma unroll 8
    for (int e = 0; e < NE; e++) {
        float nv = ns[e];
        p = fmaf(nv, W1[e * NH + t], p);
        q = fmaf(nv, W1[(NE + e) * NH + t], q);
    }
    g_P[row * NH + t] = p;
    g_Q[row * NH + t] = q;
}

__global__ void prep_Bh(const float* __restrict__ W1, const float* __restrict__ b1,
                        const float* __restrict__ W2, const float* __restrict__ b2) {
    int idx = blockIdx.x * 256 + threadIdx.x;    // 0 .. 14*8192-1
    bool isB1 = idx < 5 * 8192;
    int local = isB1 ? idx : idx - 5 * 8192;
    int c = local >> 13, n = (local >> 5) & 255, kk = local & 31;
    int k = c * 32 + kk;
    if (isB1) {
        float v = (k < 128) ? W1[(256 + k) * NH + n]
                : (k == 128) ? W1[384 * NH + n]     // euclid coeff (A col = d)
                : (k == 129) ? b1[n] : 0.f;          // bias (A col = 1)
        g_B1h[local] = __float2half_rn(v);
    } else {
        float v = (k < 256) ? W2[k * NH + n]
                : (k == 256) ? b2[n] : 0.f;          // b2 (A col = 1)
        g_B2h[local] = __float2half_rn(v);
    }
}

// ---------------- GEMM inner: one 32-k chunk = 2 k16 steps ----------------
__device__ __forceinline__ void mma_chunk2(float (&acc)[4][8][4],
                                           uint32_t aK, uint32_t bB) {
#pragma unroll
    for (int ks = 0; ks < 2; ks++) {
        uint32_t a[4][4], bf[8][2];
        uint32_t aa = aK + ks * 32;       // +16 halves
        uint32_t ba = bB + ks * 32;
#pragma unroll
        for (int mt = 0; mt < 4; mt++) LDSM4(a[mt], aa + mt * 16 * STRA_B);
#pragma unroll
        for (int nt = 0; nt < 8; nt++) LDSM2(bf[nt], ba + nt * 8 * STRB_B);
#pragma unroll
        for (int mt = 0; mt < 4; mt++)
#pragma unroll
            for (int nt = 0; nt < 8; nt++) MMA_F16(acc[mt][nt], a[mt], bf[nt]);
    }
}

// ---------------- main fused kernel ----------------
__global__ void __launch_bounds__(256, 1)
edge_mlp_mma(const float* __restrict__ node, const float* __restrict__ euclid,
             const float* __restrict__ W3, const float* __restrict__ b3) {
    extern __shared__ char smc[];
    __half* smA  = (__half*)(smc + OFF_A);
    float* P_s   = (float*)(smc + OFF_P);
    float* w3_s  = (float*)(smc + OFF_W3);
    float* ni_s  = (float*)(smc + OFF_NI);
    float* red_s = (float*)(smc + OFF_RED);
    const uint32_t sb = smem_u32(smc);

    const int tid = threadIdx.x, L = tid & 31, wid = tid >> 5;
    const int mw = wid >> 2, nw = wid & 3;
    const int m0 = mw * 64, n0 = nw * 64;
    const int b = blockIdx.z, i = blockIdx.y, j0 = blockIdx.x << 7;

    // prefetch L1 chunk 0 -> buf0 (overlaps A staging)
    {
        const __half* src = g_B1h;
#pragma unroll
        for (int r = 0; r < 4; r++) {
            int seg = tid + r * 256, n = seg >> 2, s = seg & 3;
            CP16(sb + OFF_B + n * STRB_B + s * 16, src + n * 32 + s * 8);
        }
        CPCOMMIT();
    }

    // stage small vectors
    P_s[tid]  = g_P[(b * NN + i) * NH + tid];
    w3_s[tid] = W3[tid];
    if (tid < NE) ni_s[tid] = node[(size_t)(b * NN + i) * NE + tid];
    __syncthreads();

    // ---- stage A (L1): rows = 128 j-pairs, cols [habs(128) | d | 1 | 0..(k160)]
    {
        int row = tid >> 1, half = tid & 1;
        const float4* nj = (const float4*)(node + (size_t)(b * NN + j0 + row) * NE);
        __half* dst = (__half*)((char*)smA + row * STRA_B) + half * 64;
        const float* nip = ni_s + half * 64;
#pragma unroll 8
        for (int q = 0; q < 16; q++) {
            float4 v = nj[half * 16 + q];
            __half2 h0 = __floats2half2_rn(fabsf(nip[q * 4 + 0] - v.x),
                                           fabsf(nip[q * 4 + 1] - v.y));
            __half2 h1v = __floats2half2_rn(fabsf(nip[q * 4 + 2] - v.z),
                                            fabsf(nip[q * 4 + 3] - v.w));
            *(__half2*)(dst + q * 4)     = h0;
            *(__half2*)(dst + q * 4 + 2) = h1v;
        }
        if (tid < 128) {
            float d = euclid[(size_t)(b * NN + i) * NN + j0 + tid];
            __half* rr = (__half*)((char*)smA + tid * STRA_B);
            rr[128] = __float2half_rn(d);
            rr[129] = __float2half_rn(1.0f);
#pragma unroll
            for (int u = 65; u < 80; u++) ((uint32_t*)rr)[u] = 0u;  // halves 130..159
        }
    }

    float acc[4][8][4];
#pragma unroll
    for (int mt = 0; mt < 4; mt++)
#pragma unroll
        for (int nt = 0; nt < 8; nt++)
#pragma unroll
            for (int r = 0; r < 4; r++) acc[mt][nt][r] = 0.f;

    // per-thread ldmatrix bases
    const uint32_t rowA = (L & 7) + ((L >> 3) & 1) * 8;
    const uint32_t colA = (L >> 4) * 16;
    const uint32_t aBase = sb + OFF_A + (m0 + rowA) * STRA_B + colA;
    const uint32_t bOff = (n0 + (L & 7)) * STRB_B + ((L >> 3) & 1) * 16;

    // ---- one GEMM layer over 32-k chunks, double-buffered B via cp.async ----
    auto run_layer = [&](const __half* gB, int nch, const __half* nextB, int phase) {
        for (int c = 0; c < nch; c++) {
            const __half* pre = (c + 1 < nch) ? (gB + (c + 1) * 8192) : nextB;
            if (pre) {
                uint32_t dst = sb + OFF_B + (((c + 1 + phase) & 1) ? BCHUNK_B : 0);
#pragma unroll
                for (int r = 0; r < 4; r++) {
                    int seg = tid + r * 256, n = seg >> 2, s = seg & 3;
                    CP16(dst + n * STRB_B + s * 16, pre + n * 32 + s * 8);
                }
            }
            CPCOMMIT();
            CPWAIT1();
            __syncthreads();
            uint32_t bBase = sb + OFF_B + (((c + phase) & 1) ? BCHUNK_B : 0) + bOff;
            mma_chunk2(acc, aBase + c * 64, bBase);
            __syncthreads();   // WAR fence before this buffer is rewritten
        }
    };

    run_layer(g_B1h, 5, g_B2h, 0);   // last iter prefetches L2 chunk0 -> buf1

    // ---- epilogue 1: h1 = relu(acc + P[i] + Q[j]) -> fp16 A tile in place ----
#pragma unroll
    for (int mt = 0; mt < 4; mt++) {
        int r0 = m0 + mt * 16 + (L >> 2);
        const float* qA = g_Q + ((size_t)(b * NN + j0 + r0)) * NH;
        const float* qB = qA + 8 * NH;
#pragma unroll
        for (int nt = 0; nt < 8; nt++) {
            int cb = n0 + nt * 8 + (L & 3) * 2;
            float p0 = P_s[cb], p1 = P_s[cb + 1];
            float2 qa = *(const float2*)(qA + cb);
            float2 qb = *(const float2*)(qB + cb);
            __half2 v0 = __floats2half2_rn(fmaxf(acc[mt][nt][0] + p0 + qa.x, 0.f),
                                           fmaxf(acc[mt][nt][1] + p1 + qa.y, 0.f));
            __half2 v1 = __floats2half2_rn(fmaxf(acc[mt][nt][2] + p0 + qb.x, 0.f),
                                           fmaxf(acc[mt][nt][3] + p1 + qb.y, 0.f));
            *(__half2*)((char*)smA + r0 * STRA_B + cb * 2) = v0;
            *(__half2*)((char*)smA + (r0 + 8) * STRA_B + cb * 2) = v1;
            acc[mt][nt][0] = 0.f; acc[mt][nt][1] = 0.f;
            acc[mt][nt][2] = 0.f; acc[mt][nt][3] = 0.f;
        }
    }
    if (tid < 128) {
        __half* rr = (__half*)((char*)smA + tid * STRA_B);
        rr[256] = __float2half_rn(1.0f);   // bias column for L2
        rr[257] = __float2half_rn(0.0f);
#pragma unroll
        for (int u = 129; u < 144; u++) ((uint32_t*)rr)[u] = 0u;  // halves 258..287
    }
    __syncthreads();

    run_layer(g_B2h, 9, nullptr, 5);

    // ---- epilogue 2: out = relu(acc) . W3  (b2 folded via 1-column) ----
    float w3c[16];
#pragma unroll
    for (int nt = 0; nt < 8; nt++) {
        int cb = n0 + nt * 8 + (L & 3) * 2;
        w3c[nt * 2] = w3_s[cb];
        w3c[nt * 2 + 1] = w3_s[cb + 1];
    }
    float rs[8];
#pragma unroll
    for (int mt = 0; mt < 4; mt++) {
        float s0 = 0.f, s1 = 0.f;
#pragma unroll
        for (int nt = 0; nt < 8; nt++) {
            s0 = fmaf(fmaxf(acc[mt][nt][0], 0.f), w3c[nt * 2], s0);
            s0 = fmaf(fmaxf(acc[mt][nt][1], 0.f), w3c[nt * 2 + 1], s0);
            s1 = fmaf(fmaxf(acc[mt][nt][2], 0.f), w3c[nt * 2], s1);
            s1 = fmaf(fmaxf(acc[mt][nt][3], 0.f), w3c[nt * 2 + 1], s1);
        }
        rs[mt * 2] = s0;
        rs[mt * 2 + 1] = s1;
    }
#pragma unroll
    for (int r = 0; r < 8; r++) {
        float v = rs[r];
        v += __shfl_xor_sync(0xffffffffu, v, 1);
        v += __shfl_xor_sync(0xffffffffu, v, 2);
        if ((L & 3) == 0) {
            int m = m0 + (r >> 1) * 16 + (r & 1) * 8 + (L >> 2);
            red_s[m * 4 + nw] = v;
        }
    }
    __syncthreads();
    if (tid < 128) {
        float o = red_s[tid * 4] + red_s[tid * 4 + 1] +
                  red_s[tid * 4 + 2] + red_s[tid * 4 + 3] + b3[0];
        g_raw[(size_t)(b * NN + i) * NN + j0 + tid] = o;
    }
}

// ---------------- symmetrize + zero diagonal ----------------
__global__ void symmetrize(float* __restrict__ out) {
    int idx = blockIdx.x * 256 + threadIdx.x;
    int b = idx >> 18;
    int r = idx & 262143;
    int i = r >> 9;
    int j = r & 511;
    float v = 0.f;
    if (i != j)
        v = 0.5f * (g_raw[idx] + g_raw[(b << 18) + (j << 9) + i]);
    out[idx] = v;
}

extern "C" void kernel_launch(void* const* d_in, const int* in_sizes, int n_in,
                              void* d_out, int out_size) {
    const float* node   = (const float*)d_in[0];
    const float* euclid = (const float*)d_in[2];
    const float* W1 = (const float*)d_in[3];
    const float* b1 = (const float*)d_in[4];
    const float* W2 = (const float*)d_in[5];
    const float* b2 = (const float*)d_in[6];
    const float* W3 = (const float*)d_in[7];
    const float* b3 = (const float*)d_in[8];
    float* out = (float*)d_out;

    cudaFuncSetAttribute(edge_mlp_mma, cudaFuncAttributeMaxDynamicSharedMemorySize,
                         SMEM_REQ);

    precompute_PQ<<<NB * NN, 256>>>(node, W1);
    prep_Bh<<<448, 256>>>(W1, b1, W2, b2);
    dim3 grid(NN / 128, NN, NB);
    edge_mlp_mma<<<grid, 256, SMEM_REQ>>>(node, euclid, W3, b3);
    symmetrize<<<(NB * NN * NN) / 256, 256>>>(out);
}